// round 3
// baseline (speedup 1.0000x reference)
#include <cuda_runtime.h>
#include <math.h>

#define BB 64
#define SS 128
#define FF 16
#define HH 64
#define G4H 256
#define QN 192

// ---------------- scratch (static device globals; no allocation) -------------
__device__ float g_lstm[2][FF][BB][SS][HH];      // 67 MB
__device__ float g_comb[BB][2 * FF * HH];        // 512 KB

// ---------------- helpers ----------------------------------------------------
__device__ __forceinline__ float sigm_f(float x) {
    return __fdividef(1.f, 1.f + __expf(-x));
}
__device__ __forceinline__ float tanh_f(float x) {
    x = fminf(fmaxf(x, -10.f), 10.f);
    float e = __expf(2.f * x);
    return __fdividef(e - 1.f, e + 1.f);
}

// ---------------- LSTM kernel ------------------------------------------------
// grid (8, 16, 2): x = batch-chunk of 8, y = feature, z = branch. 256 threads.
#define LSTM_SMEM ((256*64 + 8*64 + 8*64 + 8*256 + 8) * 4)

__global__ void __launch_bounds__(256) lstm_kernel(
    const float* __restrict__ x0, const float* __restrict__ x1,
    const float* __restrict__ Wih0, const float* __restrict__ Whh0,
    const float* __restrict__ bih0, const float* __restrict__ bhh0,
    const float* __restrict__ Wih1, const float* __restrict__ Whh1,
    const float* __restrict__ bih1, const float* __restrict__ bhh1)
{
    extern __shared__ float sm[];
    float4* wh4  = (float4*)sm;                 // [256][16], swizzled
    float*  h_sh = sm + 256 * 64;               // [8][64]
    float*  c_sh = h_sh + 8 * 64;               // [8][64]
    float*  g_sh = c_sh + 8 * 64;               // [8][256]
    float*  xs   = g_sh + 8 * 256;              // [8]

    const int t  = threadIdx.x;                 // gate index g
    const int f  = blockIdx.y;
    const int b0 = blockIdx.x * 8;
    const int br = blockIdx.z;

    const float* x   = br ? x1   : x0;
    const float* Wih = br ? Wih1 : Wih0;
    const float* Whh = br ? Whh1 : Whh0;
    const float* bih = br ? bih1 : bih0;
    const float* bhh = br ? bhh1 : bhh0;

    // load Whh row g=t (64 floats) with float4 chunk swizzle (conflict-free reads)
    const float4* wrow = (const float4*)(Whh + (f * G4H + t) * HH);
    #pragma unroll
    for (int c = 0; c < 16; c++)
        wh4[t * 16 + (c ^ (t & 7))] = wrow[c];

    const float wih_r  = Wih[f * G4H + t];
    const float bias_r = bih[f * G4H + t] + bhh[f * G4H + t];

    for (int i = t; i < 8 * 64; i += 256) { h_sh[i] = 0.f; c_sh[i] = 0.f; }
    __syncthreads();

    float* outbase = &g_lstm[br][f][b0][0][0];   // [8][S][H] slab

    for (int s = 0; s < SS; s++) {
        if (t < 8) xs[t] = x[((b0 + t) * SS + s) * FF + f];
        __syncthreads();   // h_sh from prev epilogue + xs ready

        float acc[8];
        #pragma unroll
        for (int b = 0; b < 8; b++) acc[b] = fmaf(xs[b], wih_r, bias_r);

        const float4* h4 = (const float4*)h_sh;
        #pragma unroll
        for (int hc = 0; hc < 16; hc++) {
            float4 w = wh4[t * 16 + (hc ^ (t & 7))];
            #pragma unroll
            for (int b = 0; b < 8; b++) {
                float4 hv = h4[b * 16 + hc];     // broadcast
                acc[b] = fmaf(w.x, hv.x, acc[b]);
                acc[b] = fmaf(w.y, hv.y, acc[b]);
                acc[b] = fmaf(w.z, hv.z, acc[b]);
                acc[b] = fmaf(w.w, hv.w, acc[b]);
            }
        }
        #pragma unroll
        for (int b = 0; b < 8; b++) g_sh[b * 256 + t] = acc[b];
        __syncthreads();

        // epilogue: 512 cells, 2 per thread
        #pragma unroll
        for (int ci = 0; ci < 2; ci++) {
            int idx = t + ci * 256;
            int b = idx >> 6;
            int j = idx & 63;
            float gi = g_sh[b * 256 + j];
            float gf = g_sh[b * 256 + 64 + j];
            float gg = g_sh[b * 256 + 128 + j];
            float go = g_sh[b * 256 + 192 + j];
            float cc = sigm_f(gf) * c_sh[b * 64 + j] + sigm_f(gi) * tanh_f(gg);
            float hh = sigm_f(go) * tanh_f(cc);
            c_sh[b * 64 + j] = cc;
            h_sh[b * 64 + j] = hh;
            outbase[(b * SS + s) * HH + j] = hh;
        }
        // top-of-loop barrier separates h_sh writes from next gates reads
    }
}

// ---------------- fused QKV + attention core ---------------------------------
// block per (b, f, branch). Computes QKV in-block from the LSTM slab, then
// scores + softmax + head-mean probs to d_out, and
// pooled = ((colmean(P) @ V) @ Wout^T + bout) to g_comb.
// pads: Xs/Wsh rows 68 (float4 access, 16B-aligned); Q/K/V rows 65 (scalar).
#define XPAD 68
#define ATTN_SMEM ((128*XPAD + 3 * 128 * 65 + 192 * 68 + 16 * 128 + 128 + 64) * 4)

__global__ void __launch_bounds__(256) attn_kernel(
    const float* __restrict__ Wq0, const float* __restrict__ bq0,
    const float* __restrict__ Wo0, const float* __restrict__ bo0,
    const float* __restrict__ Wq1, const float* __restrict__ bq1,
    const float* __restrict__ Wo1, const float* __restrict__ bo1,
    float* __restrict__ d_out)
{
    extern __shared__ float sm[];
    float* Xs   = sm;                  // [128][68]  (float4-aligned rows)
    float* Qs   = Xs + 128 * XPAD;     // [128][65]
    float* Ks   = Qs + 128 * 65;
    float* Vs   = Ks + 128 * 65;
    float* Wsh  = Vs + 128 * 65;       // [192][68]
    float* psum = Wsh + 192 * 68;      // [16][128]
    float* pbar = psum + 16 * 128;     // [128]
    float* obar = pbar + 128;          // [64]

    const int tid = threadIdx.x;
    const int tx = tid & 15, ty = tid >> 4;
    const int b = blockIdx.x, f = blockIdx.y, br = blockIdx.z;

    const float* Wq   = br ? Wq1 : Wq0;
    const float* bq   = br ? bq1 : bq0;
    const float* Wout = br ? Wo1 : Wo0;
    const float* bout = br ? bo1 : bo0;

    // ---- stage X [128][64] and W [192][64] ----
    const float4* X4 = (const float4*)(&g_lstm[br][f][b][0][0]);
    #pragma unroll
    for (int l = 0; l < 8; l++) {
        int li = tid + l * 256;          // 0..2047
        int s = li >> 4, c4 = li & 15;
        float4 v = X4[li];
        *(float4*)&Xs[s * XPAD + c4 * 4] = v;
    }
    const float4* W4 = (const float4*)(Wq + (size_t)f * QN * HH);
    #pragma unroll
    for (int l = 0; l < 12; l++) {
        int li = tid + l * 256;          // 0..3071
        int g = li >> 4, c4 = li & 15;
        float4 v = W4[li];
        *(float4*)&Wsh[g * 68 + c4 * 4] = v;
    }
    __syncthreads();

    // ---- QKV GEMM: C[128][192] = X @ W^T + bias ----
    // thread: rows s = ty*8+i, cols g = tx + 16*j (j<12)
    {
        float acc[8][12];
        #pragma unroll
        for (int j = 0; j < 12; j++) {
            float bj = bq[f * QN + tx + 16 * j];
            #pragma unroll
            for (int i = 0; i < 8; i++) acc[i][j] = bj;
        }
        #pragma unroll
        for (int k4 = 0; k4 < 16; k4++) {
            float4 wv[12];
            #pragma unroll
            for (int j = 0; j < 12; j++)
                wv[j] = *(const float4*)&Wsh[(tx + 16 * j) * 68 + k4 * 4];
            #pragma unroll
            for (int i = 0; i < 8; i++) {
                float4 xv = *(const float4*)&Xs[(ty * 8 + i) * XPAD + k4 * 4];
                #pragma unroll
                for (int j = 0; j < 12; j++) {
                    acc[i][j] = fmaf(xv.x, wv[j].x, acc[i][j]);
                    acc[i][j] = fmaf(xv.y, wv[j].y, acc[i][j]);
                    acc[i][j] = fmaf(xv.z, wv[j].z, acc[i][j]);
                    acc[i][j] = fmaf(xv.w, wv[j].w, acc[i][j]);
                }
            }
        }
        __syncthreads();   // ordering: QKV writes below vs staged reads above
        #pragma unroll
        for (int i = 0; i < 8; i++) {
            int s = ty * 8 + i;
            #pragma unroll
            for (int j = 0; j < 4; j++)  Qs[s * 65 + tx + 16 * j] = acc[i][j];
            #pragma unroll
            for (int j = 4; j < 8; j++)  Ks[s * 65 + tx + 16 * (j - 4)] = acc[i][j];
            #pragma unroll
            for (int j = 8; j < 12; j++) Vs[s * 65 + tx + 16 * (j - 8)] = acc[i][j];
        }
    }
    __syncthreads();

    float* attn_base = d_out + 128 + (size_t)br * FF * BB * SS * SS
                     + ((size_t)(f * BB + b)) * SS * SS;
    const float scale = 0.17677669529663687f;  // 1/sqrt(32)

    float p0[8][8];                    // head-0 probs held in regs

    for (int n = 0; n < 2; n++) {
        const int off = n * 32;
        float c[8][8];
        #pragma unroll
        for (int i = 0; i < 8; i++)
            #pragma unroll
            for (int j = 0; j < 8; j++) c[i][j] = 0.f;

        #pragma unroll 4
        for (int d = 0; d < 32; d++) {
            float a[8], kk[8];
            #pragma unroll
            for (int i = 0; i < 8; i++) a[i] = Qs[(ty * 8 + i) * 65 + off + d];
            #pragma unroll
            for (int j = 0; j < 8; j++) kk[j] = Ks[(tx + 16 * j) * 65 + off + d];
            #pragma unroll
            for (int i = 0; i < 8; i++)
                #pragma unroll
                for (int j = 0; j < 8; j++) c[i][j] = fmaf(a[i], kk[j], c[i][j]);
        }

        // scale + row softmax (row held by 16 lanes within one warp-half)
        #pragma unroll
        for (int i = 0; i < 8; i++) {
            float m = c[i][0] * scale;
            #pragma unroll
            for (int j = 0; j < 8; j++) { c[i][j] *= scale; m = fmaxf(m, c[i][j]); }
            #pragma unroll
            for (int o = 8; o >= 1; o >>= 1)
                m = fmaxf(m, __shfl_xor_sync(0xffffffffu, m, o, 16));
            float s2 = 0.f;
            #pragma unroll
            for (int j = 0; j < 8; j++) { c[i][j] = __expf(c[i][j] - m); s2 += c[i][j]; }
            #pragma unroll
            for (int o = 8; o >= 1; o >>= 1)
                s2 += __shfl_xor_sync(0xffffffffu, s2, o, 16);
            float inv = __fdividef(1.f, s2);
            #pragma unroll
            for (int j = 0; j < 8; j++) c[i][j] *= inv;
        }

        // head-mean probs: hold head0 in regs, single store at head1
        float colsum[8];
        #pragma unroll
        for (int j = 0; j < 8; j++) colsum[j] = 0.f;
        #pragma unroll
        for (int i = 0; i < 8; i++) {
            float* ab = attn_base + (ty * 8 + i) * SS;
            #pragma unroll
            for (int j = 0; j < 8; j++) {
                float p = c[i][j];
                colsum[j] += p;
                if (n == 0) p0[i][j] = p;
                else        ab[tx + 16 * j] = 0.5f * (p0[i][j] + p);
            }
        }
        #pragma unroll
        for (int j = 0; j < 8; j++) psum[ty * 128 + tx + 16 * j] = colsum[j];
        __syncthreads();

        if (tid < 128) {
            float s2 = 0.f;
            #pragma unroll
            for (int yy = 0; yy < 16; yy++) s2 += psum[yy * 128 + tid];
            pbar[tid] = s2 * (1.f / 128.f);
        }
        __syncthreads();
        if (tid < 32) {
            float acc = 0.f;
            #pragma unroll 8
            for (int k = 0; k < 128; k++)
                acc = fmaf(pbar[k], Vs[k * 65 + off + tid], acc);
            obar[off + tid] = acc;
        }
        __syncthreads();
    }

    // pooled = obar @ Wout^T + bout ; Wout staged in (freed) Qs, row pad 65 (scalar)
    const float* W = Wout + (size_t)f * 64 * 64;
    #pragma unroll
    for (int l = 0; l < 4; l++) {
        int li = tid + l * 256;          // 0..1023 float4s
        int j = li >> 4, hc = li & 15;
        float4 v = ((const float4*)(W + j * 64))[hc];
        Qs[j * 65 + hc * 4 + 0] = v.x;
        Qs[j * 65 + hc * 4 + 1] = v.y;
        Qs[j * 65 + hc * 4 + 2] = v.z;
        Qs[j * 65 + hc * 4 + 3] = v.w;
    }
    __syncthreads();
    if (tid < 64) {
        float acc = bout[f * 64 + tid];
        #pragma unroll 8
        for (int h2 = 0; h2 < 64; h2++)
            acc = fmaf(obar[h2], Qs[tid * 65 + h2], acc);
        g_comb[b][br * (FF * HH) + f * HH + tid] = acc;
    }
}

// ---------------- final: static/time MLPs + fc --------------------------------
__global__ void final_kernel(
    const float* __restrict__ stat,  // [B,32]
    const float* __restrict__ tg,    // [B,1]
    const float* __restrict__ d1w, const float* __restrict__ d1b,
    const float* __restrict__ d2w, const float* __restrict__ d2b,
    const float* __restrict__ t1w, const float* __restrict__ t1b,
    const float* __restrict__ t2w, const float* __restrict__ t2b,
    const float* __restrict__ fcw, const float* __restrict__ fcb,
    float* __restrict__ out)
{
    __shared__ float s1[64], t1s[16], tail[40], red[2][128];
    const int b = blockIdx.x, t = threadIdx.x;  // 128 threads

    if (t < 64) {
        float a = d1b[t];
        #pragma unroll
        for (int i = 0; i < 32; i++) a = fmaf(stat[b * 32 + i], d1w[t * 32 + i], a);
        s1[t] = fmaxf(a, 0.f);
    }
    if (t < 16) t1s[t] = fmaxf(fmaf(tg[b], t1w[t], t1b[t]), 0.f);
    __syncthreads();
    if (t < 32) {
        float a = d2b[t];
        #pragma unroll
        for (int i = 0; i < 64; i++) a = fmaf(s1[i], d2w[t * 64 + i], a);
        tail[t] = fmaxf(a, 0.f);
    }
    if (t >= 32 && t < 40) {
        int j = t - 32;
        float a = t2b[j];
        #pragma unroll
        for (int i = 0; i < 16; i++) a = fmaf(t1s[i], t2w[j * 16 + i], a);
        tail[t] = fmaxf(a, 0.f);
    }
    __syncthreads();

    float a0 = 0.f, a1 = 0.f;
    for (int c = t; c < 2088; c += 128) {
        float v = (c < 2048) ? g_comb[b][c] : tail[c - 2048];
        a0 = fmaf(v, fcw[c], a0);
        a1 = fmaf(v, fcw[2088 + c], a1);
    }
    red[0][t] = a0; red[1][t] = a1;
    __syncthreads();
    for (int off = 64; off >= 1; off >>= 1) {
        if (t < off) { red[0][t] += red[0][t + off]; red[1][t] += red[1][t + off]; }
        __syncthreads();
    }
    if (t == 0) {
        out[b * 2 + 0] = red[0][0] + fcb[0];
        out[b * 2 + 1] = red[1][0] + fcb[1];
    }
}

// ---------------- launch ------------------------------------------------------
extern "C" void kernel_launch(void* const* d_in, const int* in_sizes, int n_in,
                              void* d_out, int out_size)
{
    (void)in_sizes; (void)n_in; (void)out_size;
    float* out = (float*)d_out;

    cudaFuncSetAttribute(lstm_kernel, cudaFuncAttributeMaxDynamicSharedMemorySize, LSTM_SMEM);
    cudaFuncSetAttribute(attn_kernel, cudaFuncAttributeMaxDynamicSharedMemorySize, ATTN_SMEM);

    // LSTM: both branches in one grid (z = branch)
    lstm_kernel<<<dim3(8, 16, 2), 256, LSTM_SMEM>>>(
        (const float*)d_in[0], (const float*)d_in[1],
        (const float*)d_in[4], (const float*)d_in[5],
        (const float*)d_in[6], (const float*)d_in[7],
        (const float*)d_in[8], (const float*)d_in[9],
        (const float*)d_in[10], (const float*)d_in[11]);

    // fused QKV + attention, both branches
    attn_kernel<<<dim3(64, 16, 2), 256, ATTN_SMEM>>>(
        (const float*)d_in[12], (const float*)d_in[13],
        (const float*)d_in[14], (const float*)d_in[15],
        (const float*)d_in[16], (const float*)d_in[17],
        (const float*)d_in[18], (const float*)d_in[19],
        out);

    // final MLPs + fc
    final_kernel<<<64, 128>>>(
        (const float*)d_in[2], (const float*)d_in[3],
        (const float*)d_in[20], (const float*)d_in[21],
        (const float*)d_in[22], (const float*)d_in[23],
        (const float*)d_in[24], (const float*)d_in[25],
        (const float*)d_in[26], (const float*)d_in[27],
        (const float*)d_in[28], (const float*)d_in[29],
        out);
}

// round 6
// speedup vs baseline: 1.2262x; 1.2262x over previous
#include <cuda_runtime.h>
#include <math.h>

#define BB 64
#define SS 128
#define FF 16
#define HH 64
#define G4H 256
#define QN 192

// ---------------- scratch (static device globals; no allocation) -------------
__device__ float g_lstm[2][FF][BB][SS][HH];      // 67 MB
__device__ float g_comb[BB][2 * FF * HH];        // 512 KB

// ---------------- helpers ----------------------------------------------------
__device__ __forceinline__ float sigm_f(float x) {
    return __fdividef(1.f, 1.f + __expf(-x));
}
__device__ __forceinline__ float tanh_f(float x) {
    x = fminf(fmaxf(x, -10.f), 10.f);
    float e = __expf(2.f * x);
    return __fdividef(e - 1.f, e + 1.f);
}

// ---------------- LSTM kernel ------------------------------------------------
// grid (16, 16, 2): x = batch-chunk of 4, y = feature, z = branch. 256 threads.
// Weights register-resident (64 floats/thread). Per-step x prefetch.
#define LCH 4

__global__ void __launch_bounds__(256, 2) lstm_kernel(
    const float* __restrict__ x0, const float* __restrict__ x1,
    const float* __restrict__ Wih0, const float* __restrict__ Whh0,
    const float* __restrict__ bih0, const float* __restrict__ bhh0,
    const float* __restrict__ Wih1, const float* __restrict__ Whh1,
    const float* __restrict__ bih1, const float* __restrict__ bhh1)
{
    __shared__ float h_sh[LCH * 64];
    __shared__ float c_sh[LCH * 64];
    __shared__ float g_sh[LCH * 256];
    __shared__ float xs[LCH];

    const int t  = threadIdx.x;                 // gate index
    const int f  = blockIdx.y;
    const int b0 = blockIdx.x * LCH;
    const int br = blockIdx.z;

    const float* x   = br ? x1   : x0;
    const float* Wih = br ? Wih1 : Wih0;
    const float* Whh = br ? Whh1 : Whh0;
    const float* bih = br ? bih1 : bih0;
    const float* bhh = br ? bhh1 : bhh0;

    // register-resident Whh row for gate t (64 floats)
    float4 w[16];
    const float4* wrow = (const float4*)(Whh + (f * G4H + t) * HH);
    #pragma unroll
    for (int c = 0; c < 16; c++) w[c] = wrow[c];

    const float wih_r  = Wih[f * G4H + t];
    const float bias_r = bih[f * G4H + t] + bhh[f * G4H + t];

    for (int i = t; i < LCH * 64; i += 256) { h_sh[i] = 0.f; c_sh[i] = 0.f; }
    if (t < LCH) xs[t] = x[((b0 + t) * SS + 0) * FF + f];
    __syncthreads();

    float* outbase = &g_lstm[br][f][b0][0][0];   // [LCH][S][H] slab
    const int bb = t >> 6, jj = t & 63;          // epilogue cell

    float xnext = 0.f;
    for (int s = 0; s < SS; s++) {
        // prefetch next step's x (latency hidden under the gates GEMM)
        if (t < LCH && s + 1 < SS) xnext = x[((b0 + t) * SS + s + 1) * FF + f];

        float acc[LCH];
        #pragma unroll
        for (int b = 0; b < LCH; b++) acc[b] = fmaf(xs[b], wih_r, bias_r);

        const float4* h4 = (const float4*)h_sh;
        #pragma unroll
        for (int hc = 0; hc < 16; hc++) {
            float4 wv = w[hc];
            #pragma unroll
            for (int b = 0; b < LCH; b++) {
                float4 hv = h4[b * 16 + hc];     // broadcast
                acc[b] = fmaf(wv.x, hv.x, acc[b]);
                acc[b] = fmaf(wv.y, hv.y, acc[b]);
                acc[b] = fmaf(wv.z, hv.z, acc[b]);
                acc[b] = fmaf(wv.w, hv.w, acc[b]);
            }
        }
        #pragma unroll
        for (int b = 0; b < LCH; b++) g_sh[b * 256 + t] = acc[b];
        __syncthreads();

        // epilogue: one cell per thread
        {
            float gi = g_sh[bb * 256 + jj];
            float gf = g_sh[bb * 256 + 64 + jj];
            float gg = g_sh[bb * 256 + 128 + jj];
            float go = g_sh[bb * 256 + 192 + jj];
            float cc = sigm_f(gf) * c_sh[bb * 64 + jj] + sigm_f(gi) * tanh_f(gg);
            float hh = sigm_f(go) * tanh_f(cc);
            c_sh[bb * 64 + jj] = cc;
            h_sh[bb * 64 + jj] = hh;
            outbase[(bb * SS + s) * HH + jj] = hh;
        }
        if (t < LCH) xs[t] = xnext;
        __syncthreads();
    }
}

// ---------------- fused QK + attention core (V eliminated) -------------------
// block per (b, f, branch), 512 threads. Computes Q,K in-block, scores,
// softmax, head-mean probs to d_out; pooled via pbar@X@Wv^T trick.
#define XPAD 68
#define ATTN_SMEM ((128*XPAD + 128*XPAD + 64*XPAD + 2*128*65 + 32*128 + 128 + 64 + 64) * 4)

__global__ void __launch_bounds__(512, 1) attn_kernel(
    const float* __restrict__ Wq0, const float* __restrict__ bq0,
    const float* __restrict__ Wo0, const float* __restrict__ bo0,
    const float* __restrict__ Wq1, const float* __restrict__ bq1,
    const float* __restrict__ Wo1, const float* __restrict__ bo1,
    float* __restrict__ d_out)
{
    extern __shared__ float sm[];
    float* Xs   = sm;                      // [128][68]
    float* Wsh  = Xs + 128 * XPAD;         // [128][68]  Q,K weight rows
    float* Wvs  = Wsh + 128 * XPAD;        // [64][68]   V weight rows
    float* Qs   = Wvs + 64 * XPAD;         // [128][65]
    float* Ks   = Qs + 128 * 65;           // [128][65]
    float* psum = Ks + 128 * 65;           // [32][128]
    float* pbar = psum + 32 * 128;         // [128]
    float* ys   = pbar + 128;              // [64]
    float* obar = ys + 64;                 // [64]

    const int tid = threadIdx.x;
    const int tx = tid & 15, ty = tid >> 4;   // ty: 0..31
    const int b = blockIdx.x, f = blockIdx.y, br = blockIdx.z;

    const float* Wq   = br ? Wq1 : Wq0;
    const float* bq   = br ? bq1 : bq0;
    const float* Wout = br ? Wo1 : Wo0;
    const float* bout = br ? bo1 : bo0;

    // ---- stage X [128][64], Wqk [128][64], Wv [64][64] ----
    const float4* X4 = (const float4*)(&g_lstm[br][f][b][0][0]);
    #pragma unroll
    for (int l = 0; l < 4; l++) {
        int li = tid + l * 512;              // 0..2047
        int s = li >> 4, c4 = li & 15;
        *(float4*)&Xs[s * XPAD + c4 * 4] = X4[li];
    }
    const float4* W4 = (const float4*)(Wq + (size_t)f * QN * HH);
    #pragma unroll
    for (int l = 0; l < 4; l++) {
        int li = tid + l * 512;              // rows 0..127
        int g = li >> 4, c4 = li & 15;
        *(float4*)&Wsh[g * XPAD + c4 * 4] = W4[li];
    }
    #pragma unroll
    for (int l = 0; l < 2; l++) {
        int li = tid + l * 512;              // 0..1023 -> rows 128..191
        int r = li >> 4, c4 = li & 15;
        *(float4*)&Wvs[r * XPAD + c4 * 4] = W4[2048 + li];
    }
    __syncthreads();

    // ---- QK GEMM: [128 rows][128 gate-cols] = X @ Wqk^T + bias ----
    {
        float acc[4][8];
        #pragma unroll
        for (int j = 0; j < 8; j++) {
            float bj = bq[f * QN + tx + 16 * j];
            #pragma unroll
            for (int i = 0; i < 4; i++) acc[i][j] = bj;
        }
        #pragma unroll
        for (int k4 = 0; k4 < 16; k4++) {
            float4 wv[8];
            #pragma unroll
            for (int j = 0; j < 8; j++)
                wv[j] = *(const float4*)&Wsh[(tx + 16 * j) * XPAD + k4 * 4];
            #pragma unroll
            for (int i = 0; i < 4; i++) {
                float4 xv = *(const float4*)&Xs[(ty * 4 + i) * XPAD + k4 * 4];
                #pragma unroll
                for (int j = 0; j < 8; j++) {
                    acc[i][j] = fmaf(xv.x, wv[j].x, acc[i][j]);
                    acc[i][j] = fmaf(xv.y, wv[j].y, acc[i][j]);
                    acc[i][j] = fmaf(xv.z, wv[j].z, acc[i][j]);
                    acc[i][j] = fmaf(xv.w, wv[j].w, acc[i][j]);
                }
            }
        }
        __syncthreads();
        #pragma unroll
        for (int i = 0; i < 4; i++) {
            int s = ty * 4 + i;
            #pragma unroll
            for (int j = 0; j < 4; j++) Qs[s * 65 + tx + 16 * j] = acc[i][j];
            #pragma unroll
            for (int j = 4; j < 8; j++) Ks[s * 65 + tx + 16 * (j - 4)] = acc[i][j];
        }
    }
    __syncthreads();

    float* attn_base = d_out + 128 + (size_t)br * FF * BB * SS * SS
                     + ((size_t)(f * BB + b)) * SS * SS;
    const float scale = 0.17677669529663687f;  // 1/sqrt(32)

    float p0[4][8];                    // head-0 probs in regs

    for (int n = 0; n < 2; n++) {
        const int off = n * 32;
        float c[4][8];
        #pragma unroll
        for (int i = 0; i < 4; i++)
            #pragma unroll
            for (int j = 0; j < 8; j++) c[i][j] = 0.f;

        #pragma unroll 4
        for (int d = 0; d < 32; d++) {
            float a[4], kk[8];
            #pragma unroll
            for (int i = 0; i < 4; i++) a[i] = Qs[(ty * 4 + i) * 65 + off + d];
            #pragma unroll
            for (int j = 0; j < 8; j++) kk[j] = Ks[(tx + 16 * j) * 65 + off + d];
            #pragma unroll
            for (int i = 0; i < 4; i++)
                #pragma unroll
                for (int j = 0; j < 8; j++) c[i][j] = fmaf(a[i], kk[j], c[i][j]);
        }

        // scale + row softmax (row = 16 lanes of one half-warp)
        #pragma unroll
        for (int i = 0; i < 4; i++) {
            float m = c[i][0] * scale;
            #pragma unroll
            for (int j = 0; j < 8; j++) { c[i][j] *= scale; m = fmaxf(m, c[i][j]); }
            #pragma unroll
            for (int o = 8; o >= 1; o >>= 1)
                m = fmaxf(m, __shfl_xor_sync(0xffffffffu, m, o, 16));
            float s2 = 0.f;
            #pragma unroll
            for (int j = 0; j < 8; j++) { c[i][j] = __expf(c[i][j] - m); s2 += c[i][j]; }
            #pragma unroll
            for (int o = 8; o >= 1; o >>= 1)
                s2 += __shfl_xor_sync(0xffffffffu, s2, o, 16);
            float inv = __fdividef(1.f, s2);
            #pragma unroll
            for (int j = 0; j < 8; j++) c[i][j] *= inv;
        }

        // head-mean probs + per-head column sums
        float colsum[8];
        #pragma unroll
        for (int j = 0; j < 8; j++) colsum[j] = 0.f;
        #pragma unroll
        for (int i = 0; i < 4; i++) {
            float* ab = attn_base + (ty * 4 + i) * SS;
            #pragma unroll
            for (int j = 0; j < 8; j++) {
                float p = c[i][j];
                colsum[j] += p;
                if (n == 0) p0[i][j] = p;
                else        ab[tx + 16 * j] = 0.5f * (p0[i][j] + p);
            }
        }
        #pragma unroll
        for (int j = 0; j < 8; j++) psum[ty * 128 + tx + 16 * j] = colsum[j];
        __syncthreads();

        if (tid < 128) {
            float s2 = 0.f;
            #pragma unroll
            for (int yy = 0; yy < 32; yy++) s2 += psum[yy * 128 + tid];
            pbar[tid] = s2 * (1.f / 128.f);
        }
        __syncthreads();

        // y = pbar @ X   (64 dims)
        if (tid < 64) {
            float a2 = 0.f;
            #pragma unroll 8
            for (int k = 0; k < 128; k++)
                a2 = fmaf(pbar[k], Xs[k * XPAD + tid], a2);
            ys[tid] = a2;
        }
        __syncthreads();

        // obar[head cols] = y @ Wv^T + bv  (take this head's 32 columns)
        if (tid < 32) {
            float a2 = bq[f * QN + 128 + off + tid];
            #pragma unroll 8
            for (int d = 0; d < 64; d++)
                a2 = fmaf(ys[d], Wvs[(off + tid) * XPAD + d], a2);
            obar[off + tid] = a2;
        }
        __syncthreads();
    }

    // pooled = obar @ Wout^T + bout ; Wout staged into (dead) Qs, pad 65
    const float* W = Wout + (size_t)f * 64 * 64;
    #pragma unroll
    for (int l = 0; l < 2; l++) {
        int li = tid + l * 512;              // 0..1023 float4s
        int j = li >> 4, hc = li & 15;
        float4 v = ((const float4*)(W + j * 64))[hc];
        Qs[j * 65 + hc * 4 + 0] = v.x;
        Qs[j * 65 + hc * 4 + 1] = v.y;
        Qs[j * 65 + hc * 4 + 2] = v.z;
        Qs[j * 65 + hc * 4 + 3] = v.w;
    }
    __syncthreads();
    if (tid < 64) {
        float a2 = bout[f * 64 + tid];
        #pragma unroll 8
        for (int h2 = 0; h2 < 64; h2++)
            a2 = fmaf(obar[h2], Qs[tid * 65 + h2], a2);
        g_comb[b][br * (FF * HH) + f * HH + tid] = a2;
    }
}

// ---------------- final: static/time MLPs + fc --------------------------------
__global__ void final_kernel(
    const float* __restrict__ stat,  // [B,32]
    const float* __restrict__ tg,    // [B,1]
    const float* __restrict__ d1w, const float* __restrict__ d1b,
    const float* __restrict__ d2w, const float* __restrict__ d2b,
    const float* __restrict__ t1w, const float* __restrict__ t1b,
    const float* __restrict__ t2w, const float* __restrict__ t2b,
    const float* __restrict__ fcw, const float* __restrict__ fcb,
    float* __restrict__ out)
{
    __shared__ float s1[64], t1s[16], tail[40], red[2][128];
    const int b = blockIdx.x, t = threadIdx.x;  // 128 threads

    if (t < 64) {
        float a = d1b[t];
        #pragma unroll
        for (int i = 0; i < 32; i++) a = fmaf(stat[b * 32 + i], d1w[t * 32 + i], a);
        s1[t] = fmaxf(a, 0.f);
    }
    if (t < 16) t1s[t] = fmaxf(fmaf(tg[b], t1w[t], t1b[t]), 0.f);
    __syncthreads();
    if (t < 32) {
        float a = d2b[t];
        #pragma unroll
        for (int i = 0; i < 64; i++) a = fmaf(s1[i], d2w[t * 64 + i], a);
        tail[t] = fmaxf(a, 0.f);
    }
    if (t >= 32 && t < 40) {
        int j = t - 32;
        float a = t2b[j];
        #pragma unroll
        for (int i = 0; i < 16; i++) a = fmaf(t1s[i], t2w[j * 16 + i], a);
        tail[t] = fmaxf(a, 0.f);
    }
    __syncthreads();

    float a0 = 0.f, a1 = 0.f;
    for (int c = t; c < 2088; c += 128) {
        float v = (c < 2048) ? g_comb[b][c] : tail[c - 2048];
        a0 = fmaf(v, fcw[c], a0);
        a1 = fmaf(v, fcw[2088 + c], a1);
    }
    red[0][t] = a0; red[1][t] = a1;
    __syncthreads();
    for (int off = 64; off >= 1; off >>= 1) {
        if (t < off) { red[0][t] += red[0][t + off]; red[1][t] += red[1][t + off]; }
        __syncthreads();
    }
    if (t == 0) {
        out[b * 2 + 0] = red[0][0] + fcb[0];
        out[b * 2 + 1] = red[1][0] + fcb[1];
    }
}

// ---------------- launch ------------------------------------------------------
extern "C" void kernel_launch(void* const* d_in, const int* in_sizes, int n_in,
                              void* d_out, int out_size)
{
    (void)in_sizes; (void)n_in; (void)out_size;
    float* out = (float*)d_out;

    cudaFuncSetAttribute(attn_kernel, cudaFuncAttributeMaxDynamicSharedMemorySize, ATTN_SMEM);

    // LSTM: both branches, batch-chunk 4
    lstm_kernel<<<dim3(16, 16, 2), 256>>>(
        (const float*)d_in[0], (const float*)d_in[1],
        (const float*)d_in[4], (const float*)d_in[5],
        (const float*)d_in[6], (const float*)d_in[7],
        (const float*)d_in[8], (const float*)d_in[9],
        (const float*)d_in[10], (const float*)d_in[11]);

    // fused QK + attention (V eliminated algebraically), both branches
    attn_kernel<<<dim3(64, 16, 2), 512, ATTN_SMEM>>>(
        (const float*)d_in[12], (const float*)d_in[13],
        (const float*)d_in[14], (const float*)d_in[15],
        (const float*)d_in[16], (const float*)d_in[17],
        (const float*)d_in[18], (const float*)d_in[19],
        out);

    // final MLPs + fc
    final_kernel<<<64, 128>>>(
        (const float*)d_in[2], (const float*)d_in[3],
        (const float*)d_in[20], (const float*)d_in[21],
        (const float*)d_in[22], (const float*)d_in[23],
        (const float*)d_in[24], (const float*)d_in[25],
        (const float*)d_in[26], (const float*)d_in[27],
        (const float*)d_in[28], (const float*)d_in[29],
        out);
}